// round 6
// baseline (speedup 1.0000x reference)
#include <cuda_runtime.h>
#include <cstdint>

#define D0 64
#define D1 128
#define NMAX 100000
#define EMAX 1600000
#define RPB 8

// Scratch (device globals; allocation in kernel_launch is forbidden)
__device__ __align__(16) float g_h[NMAX * D1];       // 51.2 MB
__device__ __align__(16) float g_p[NMAX * D0];       // 25.6 MB
__device__ __align__(16) int   g_idx[2 * EMAX];      // 12.8 MB
__device__ __align__(16) int   g_col[EMAX];          // 6.4 MB
__device__ int g_rowptr[NMAX + 1];
__device__ int g_cur[NMAX];
__device__ int g_cnt[NMAX];   // zero at load; re-zeroed by agg2 tail each run

// packed f32x2 FMA helpers
__device__ __forceinline__ void fma2(uint64_t& d, uint64_t a, uint64_t b) {
    asm("fma.rn.f32x2 %0, %1, %2, %0;" : "+l"(d) : "l"(a), "l"(b));
}
__device__ __forceinline__ uint64_t pack2(float v) {
    uint32_t u = __float_as_uint(v);
    uint64_t r;
    asm("mov.b64 %0, {%1, %1};" : "=l"(r) : "r"(u));
    return r;
}

// ---------------------------------------------------------------------------
// convert: per-block int64/int32 detect + normalize to int32 + row histogram
// ---------------------------------------------------------------------------
__global__ __launch_bounds__(1024) void convert_k(const void* __restrict__ ei,
                                                  int E) {
    const int* raw = (const int*)ei;
    int nz = 0;
    for (int i = 2 * threadIdx.x + 1; i < 8192; i += 2 * blockDim.x)
        nz |= raw[i];
    int any = __syncthreads_or(nz);
    bool is64 = (any == 0);

    int stride = gridDim.x * blockDim.x;
    for (int i = blockIdx.x * blockDim.x + threadIdx.x; i < 2 * E; i += stride) {
        int v = is64 ? (int)((const long long*)ei)[i] : raw[i];
        g_idx[i] = v;
        if (i < E) atomicAdd(&g_cnt[v], 1);
    }
}

// ---------------------------------------------------------------------------
// scan: one-kernel exclusive prefix scan of g_cnt -> g_rowptr, g_cur
// ---------------------------------------------------------------------------
__global__ __launch_bounds__(1024) void scan_k(int Nn, int E) {
    __shared__ int sh[1024];
    __shared__ int s_off;
    int b = blockIdx.x;

    int pre = 0;
    for (int i = threadIdx.x; i < b * 1024; i += 1024) pre += g_cnt[i];
    sh[threadIdx.x] = pre;
    __syncthreads();
    #pragma unroll
    for (int off = 512; off > 0; off >>= 1) {
        if (threadIdx.x < off) sh[threadIdx.x] += sh[threadIdx.x + off];
        __syncthreads();
    }
    if (threadIdx.x == 0) s_off = sh[0];
    __syncthreads();
    int base = s_off;
    __syncthreads();

    int g = b * 1024 + threadIdx.x;
    int v = (g < Nn) ? g_cnt[g] : 0;
    sh[threadIdx.x] = v;
    __syncthreads();
    #pragma unroll
    for (int off = 1; off < 1024; off <<= 1) {
        int t = (threadIdx.x >= off) ? sh[threadIdx.x - off] : 0;
        __syncthreads();
        sh[threadIdx.x] += t;
        __syncthreads();
    }
    if (g < Nn) {
        int r = base + sh[threadIdx.x] - v;
        g_rowptr[g] = r;
        g_cur[g] = r;
    }
    if (b == 0 && threadIdx.x == 0) g_rowptr[Nn] = E;
}

// ---------------------------------------------------------------------------
// CSR fill
// ---------------------------------------------------------------------------
__global__ void fill_k(int E) {
    int e = blockIdx.x * blockDim.x + threadIdx.x;
    if (e >= E) return;
    int r = g_idx[e];
    int c = g_idx[e + E];
    int pos = atomicAdd(&g_cur[r], 1);
    g_col[pos] = c;
}

// ---------------------------------------------------------------------------
// Fused agg1 + mm1:
//   t[r] = (sum x[c]) / deg + x[r]    (gather, staged dup-packed in smem)
//   h[r] = relu(t[r] @ W1 + b1)       (register-blocked f32x2 GEMM)
// 128 threads, 4 warps, RPB rows/warp/iter, persistent grid (592 = 1 wave).
// Dynamic smem: sW1 32KB | sb1 512B | st 4*8*64*8B = 16KB  -> 49664 B
// ---------------------------------------------------------------------------
__global__ __launch_bounds__(128) void aggmm1_k(const float* __restrict__ x,
                                                const float* __restrict__ W1,
                                                const float* __restrict__ b1,
                                                int Nn) {
    extern __shared__ char smem_[];
    float*    sW1 = (float*)smem_;                        // [k][j] 64x128
    float*    sb1 = (float*)(smem_ + 32768);
    uint64_t* st  = (uint64_t*)(smem_ + 33280);           // [warp][rr][64]

    int tid = threadIdx.x;
    for (int i = tid; i < D0 * D1; i += 128) sW1[i] = W1[i];
    if (tid < D1) sb1[tid] = b1[tid];
    __syncthreads();

    int warp = tid >> 5, lane = tid & 31;
    uint64_t* stw = st + warp * RPB * D0;
    float4 b4 = ((const float4*)sb1)[lane];
    int nwarps = gridDim.x * 4;
    int gw = blockIdx.x * 4 + warp;

    for (int base = gw * RPB; base < Nn; base += nwarps * RPB) {
        // --- gather + stage (dup-packed) ---
        #pragma unroll 1
        for (int rr = 0; rr < RPB; rr++) {
            int r = base + rr;
            if (r >= Nn) break;
            int s = g_rowptr[r], e = g_rowptr[r + 1];
            float2 acc = make_float2(0.f, 0.f);
            int j = s;
            #pragma unroll 1
            for (; j + 8 <= e; j += 8) {
                float2 v0 = __ldg(&((const float2*)x)[g_col[j]     * 32 + lane]);
                float2 v1 = __ldg(&((const float2*)x)[g_col[j + 1] * 32 + lane]);
                float2 v2 = __ldg(&((const float2*)x)[g_col[j + 2] * 32 + lane]);
                float2 v3 = __ldg(&((const float2*)x)[g_col[j + 3] * 32 + lane]);
                float2 v4 = __ldg(&((const float2*)x)[g_col[j + 4] * 32 + lane]);
                float2 v5 = __ldg(&((const float2*)x)[g_col[j + 5] * 32 + lane]);
                float2 v6 = __ldg(&((const float2*)x)[g_col[j + 6] * 32 + lane]);
                float2 v7 = __ldg(&((const float2*)x)[g_col[j + 7] * 32 + lane]);
                acc.x += ((v0.x + v1.x) + (v2.x + v3.x)) + ((v4.x + v5.x) + (v6.x + v7.x));
                acc.y += ((v0.y + v1.y) + (v2.y + v3.y)) + ((v4.y + v5.y) + (v6.y + v7.y));
            }
            for (; j < e; j++) {
                float2 v = __ldg(&((const float2*)x)[g_col[j] * 32 + lane]);
                acc.x += v.x;
                acc.y += v.y;
            }
            float inv = 1.0f / fmaxf((float)(e - s), 1.0f);
            float2 xx = __ldg(&((const float2*)x)[r * 32 + lane]);
            ulonglong2 d;
            d.x = pack2(acc.x * inv + xx.x);
            d.y = pack2(acc.y * inv + xx.y);
            ((ulonglong2*)(stw + rr * D0))[lane] = d;   // k = 2*lane, 2*lane+1
        }
        __syncwarp();

        // --- GEMM: 2-k blocking, f32x2 ---
        uint64_t accA[RPB], accB[RPB];
        #pragma unroll
        for (int rr = 0; rr < RPB; rr++) { accA[rr] = 0ull; accB[rr] = 0ull; }

        #pragma unroll 4
        for (int k2 = 0; k2 < D0; k2 += 2) {
            ulonglong2 a[RPB];
            #pragma unroll
            for (int rr = 0; rr < RPB; rr++)
                a[rr] = *(const ulonglong2*)(stw + rr * D0 + k2);   // broadcast
            #pragma unroll
            for (int kk = 0; kk < 2; kk++) {
                ulonglong2 w2 = ((const ulonglong2*)(sW1 + (k2 + kk) * D1))[lane];
                #pragma unroll
                for (int rr = 0; rr < RPB; rr++) {
                    uint64_t aa = kk ? a[rr].y : a[rr].x;
                    fma2(accA[rr], aa, w2.x);
                    fma2(accB[rr], aa, w2.y);
                }
            }
        }

        #pragma unroll
        for (int rr = 0; rr < RPB; rr++) {
            int r = base + rr;
            if (r < Nn) {
                float2 aa = *(float2*)&accA[rr];
                float2 bb = *(float2*)&accB[rr];
                float4 o;
                o.x = fmaxf(aa.x + b4.x, 0.f);
                o.y = fmaxf(aa.y + b4.y, 0.f);
                o.z = fmaxf(bb.x + b4.z, 0.f);
                o.w = fmaxf(bb.y + b4.w, 0.f);
                ((float4*)g_h)[r * 32 + lane] = o;
            }
        }
        __syncwarp();
    }
}

// ---------------------------------------------------------------------------
// mm2: p = h @ W2  [N,128]->[N,64], dup-packed A, f32x2.
// Dynamic smem: sW2 32KB | sh 4*8*128*8B = 32KB  -> 65536 B
// ---------------------------------------------------------------------------
__global__ __launch_bounds__(128) void mm2_k(const float* __restrict__ W2,
                                             int Nn) {
    extern __shared__ char smem_[];
    float*    sW2 = (float*)smem_;                        // [k][j] 128x64
    uint64_t* shh = (uint64_t*)(smem_ + 32768);           // [warp][rr][128]

    int tid = threadIdx.x;
    for (int i = tid; i < D1 * D0; i += 128) sW2[i] = W2[i];
    __syncthreads();

    int warp = tid >> 5, lane = tid & 31;
    uint64_t* shw = shh + warp * RPB * D1;
    int nwarps = gridDim.x * 4;
    int gw = blockIdx.x * 4 + warp;

    for (int base = gw * RPB; base < Nn; base += nwarps * RPB) {
        #pragma unroll
        for (int rr = 0; rr < RPB; rr++) {
            int r = base + rr;
            if (r < Nn) {
                float4 hv = ((const float4*)g_h)[r * 32 + lane];
                ulonglong2 d0, d1;
                d0.x = pack2(hv.x); d0.y = pack2(hv.y);
                d1.x = pack2(hv.z); d1.y = pack2(hv.w);
                ulonglong2* row = (ulonglong2*)(shw + rr * D1);
                row[2 * lane]     = d0;    // k = 4lane, 4lane+1
                row[2 * lane + 1] = d1;    // k = 4lane+2, 4lane+3
            }
        }
        __syncwarp();

        uint64_t acc[RPB];
        #pragma unroll
        for (int rr = 0; rr < RPB; rr++) acc[rr] = 0ull;

        #pragma unroll 4
        for (int k2 = 0; k2 < D1; k2 += 2) {
            ulonglong2 a[RPB];
            #pragma unroll
            for (int rr = 0; rr < RPB; rr++)
                a[rr] = *(const ulonglong2*)(shw + rr * D1 + k2);
            #pragma unroll
            for (int kk = 0; kk < 2; kk++) {
                uint64_t w = ((const uint64_t*)(sW2 + (k2 + kk) * D0))[lane];
                #pragma unroll
                for (int rr = 0; rr < RPB; rr++)
                    fma2(acc[rr], kk ? a[rr].y : a[rr].x, w);
            }
        }

        #pragma unroll
        for (int rr = 0; rr < RPB; rr++) {
            int r = base + rr;
            if (r < Nn) ((float2*)g_p)[r * 32 + lane] = *(float2*)&acc[rr];
        }
        __syncwarp();
    }
}

// ---------------------------------------------------------------------------
// agg2: out[r] = (sum_{c in adj(r)} p[c]) / max(deg,1) + p[r] + b2
// Tail: re-zero g_cnt for the next graph replay.
// ---------------------------------------------------------------------------
__global__ __launch_bounds__(512) void agg2_k(const float* __restrict__ b2,
                                              float* __restrict__ out, int Nn) {
    int w = (blockIdx.x * blockDim.x + threadIdx.x) >> 5;
    if (w >= Nn) return;
    int lane = threadIdx.x & 31;
    int s = g_rowptr[w], e = g_rowptr[w + 1];
    float2 acc = make_float2(0.f, 0.f);
    int j = s;
    #pragma unroll 1
    for (; j + 8 <= e; j += 8) {
        float2 v0 = ((const float2*)g_p)[g_col[j]     * 32 + lane];
        float2 v1 = ((const float2*)g_p)[g_col[j + 1] * 32 + lane];
        float2 v2 = ((const float2*)g_p)[g_col[j + 2] * 32 + lane];
        float2 v3 = ((const float2*)g_p)[g_col[j + 3] * 32 + lane];
        float2 v4 = ((const float2*)g_p)[g_col[j + 4] * 32 + lane];
        float2 v5 = ((const float2*)g_p)[g_col[j + 5] * 32 + lane];
        float2 v6 = ((const float2*)g_p)[g_col[j + 6] * 32 + lane];
        float2 v7 = ((const float2*)g_p)[g_col[j + 7] * 32 + lane];
        acc.x += ((v0.x + v1.x) + (v2.x + v3.x)) + ((v4.x + v5.x) + (v6.x + v7.x));
        acc.y += ((v0.y + v1.y) + (v2.y + v3.y)) + ((v4.y + v5.y) + (v6.y + v7.y));
    }
    for (; j < e; j++) {
        float2 v = ((const float2*)g_p)[g_col[j] * 32 + lane];
        acc.x += v.x;
        acc.y += v.y;
    }
    float inv = 1.0f / fmaxf((float)(e - s), 1.0f);
    float2 pp = ((const float2*)g_p)[w * 32 + lane];
    float2 bb = __ldg(&((const float2*)b2)[lane]);
    ((float2*)out)[w * 32 + lane] =
        make_float2(acc.x * inv + pp.x + bb.x, acc.y * inv + pp.y + bb.y);
    if (lane == 0) g_cnt[w] = 0;
}

// ---------------------------------------------------------------------------
extern "C" void kernel_launch(void* const* d_in, const int* in_sizes, int n_in,
                              void* d_out, int out_size) {
    const float* x   = (const float*)d_in[0];
    const void*  ei  = d_in[1];
    const float* W1  = (const float*)d_in[2];
    const float* b1  = (const float*)d_in[3];
    const float* W2  = (const float*)d_in[4];
    const float* b2  = (const float*)d_in[5];
    float*       out = (float*)d_out;

    int Nn = in_sizes[0] / D0;       // 100000
    int E  = in_sizes[1] / 2;        // 1600000
    int nblk_scan = (Nn + 1023) / 1024;

    const int SM1 = 33280 + 4 * RPB * D0 * 8;   // 49664 B
    const int SM2 = 32768 + 4 * RPB * D1 * 8;   // 65536 B
    cudaFuncSetAttribute(aggmm1_k, cudaFuncAttributeMaxDynamicSharedMemorySize, SM1);
    cudaFuncSetAttribute(mm2_k,    cudaFuncAttributeMaxDynamicSharedMemorySize, SM2);

    convert_k<<<296, 1024>>>(ei, E);                     // 0
    scan_k<<<nblk_scan, 1024>>>(Nn, E);                  // 1
    fill_k<<<(E + 255) / 256, 256>>>(E);                 // 2
    aggmm1_k<<<592, 128, SM1>>>(x, W1, b1, Nn);          // 3  <- profiled
    mm2_k<<<444, 128, SM2>>>(W2, Nn);                    // 4
    agg2_k<<<(Nn * 32 + 511) / 512, 512>>>(b2, out, Nn); // 5
}

// round 7
// speedup vs baseline: 1.3761x; 1.3761x over previous
#include <cuda_runtime.h>
#include <cstdint>

#define D0 64
#define D1 128
#define NMAX 100000
#define EMAX 1600000
#define RPB 8

// Scratch (device globals; allocation in kernel_launch is forbidden)
__device__ __align__(16) float g_t[NMAX * D0];       // 25.6 MB
__device__ __align__(16) float g_p[NMAX * D0];       // 25.6 MB
__device__ __align__(16) int   g_col[EMAX];          // 6.4 MB
__device__ int g_rowptr[NMAX + 1];
__device__ int g_cur[NMAX];
__device__ int g_cnt[NMAX];   // zero at load; re-zeroed by agg2 tail each run

// packed f32x2 FMA helpers
__device__ __forceinline__ void fma2(uint64_t& d, uint64_t a, uint64_t b) {
    asm("fma.rn.f32x2 %0, %1, %2, %0;" : "+l"(d) : "l"(a), "l"(b));
}
__device__ __forceinline__ uint64_t pack2(float v) {
    uint32_t u = __float_as_uint(v);
    uint64_t r;
    asm("mov.b64 %0, {%1, %1};" : "=l"(r) : "r"(u));
    return r;
}

// per-block int64-vs-int32 detect (odd 32-bit words all zero over 8192 = i64)
__device__ __forceinline__ bool detect64(const int* raw) {
    int nz = 0;
    for (int i = 2 * threadIdx.x + 1; i < 8192; i += 2 * blockDim.x)
        nz |= raw[i];
    return __syncthreads_or(nz) == 0;
}
__device__ __forceinline__ int eidx(const void* ei, bool is64, int i) {
    return is64 ? (int)((const long long*)ei)[i] : ((const int*)ei)[i];
}

// ---------------------------------------------------------------------------
// hist: row histogram straight off the raw edge list
// ---------------------------------------------------------------------------
__global__ __launch_bounds__(1024) void hist_k(const void* __restrict__ ei, int E) {
    bool is64 = detect64((const int*)ei);
    int stride = gridDim.x * blockDim.x;
    for (int i = blockIdx.x * blockDim.x + threadIdx.x; i < E; i += stride)
        atomicAdd(&g_cnt[eidx(ei, is64, i)], 1);
}

// ---------------------------------------------------------------------------
// scan: one-kernel exclusive prefix scan of g_cnt -> g_rowptr, g_cur
// ---------------------------------------------------------------------------
__global__ __launch_bounds__(1024) void scan_k(int Nn, int E) {
    __shared__ int sh[1024];
    __shared__ int s_off;
    int b = blockIdx.x;

    int pre = 0;
    for (int i = threadIdx.x; i < b * 1024; i += 1024) pre += g_cnt[i];
    sh[threadIdx.x] = pre;
    __syncthreads();
    #pragma unroll
    for (int off = 512; off > 0; off >>= 1) {
        if (threadIdx.x < off) sh[threadIdx.x] += sh[threadIdx.x + off];
        __syncthreads();
    }
    if (threadIdx.x == 0) s_off = sh[0];
    __syncthreads();
    int base = s_off;
    __syncthreads();

    int g = b * 1024 + threadIdx.x;
    int v = (g < Nn) ? g_cnt[g] : 0;
    sh[threadIdx.x] = v;
    __syncthreads();
    #pragma unroll
    for (int off = 1; off < 1024; off <<= 1) {
        int t = (threadIdx.x >= off) ? sh[threadIdx.x - off] : 0;
        __syncthreads();
        sh[threadIdx.x] += t;
        __syncthreads();
    }
    if (g < Nn) {
        int r = base + sh[threadIdx.x] - v;
        g_rowptr[g] = r;
        g_cur[g] = r;
    }
    if (b == 0 && threadIdx.x == 0) g_rowptr[Nn] = E;
}

// ---------------------------------------------------------------------------
// fill: CSR col array straight off the raw edge list
// ---------------------------------------------------------------------------
__global__ __launch_bounds__(1024) void fill_k(const void* __restrict__ ei, int E) {
    bool is64 = detect64((const int*)ei);
    int stride = gridDim.x * blockDim.x;
    for (int e = blockIdx.x * blockDim.x + threadIdx.x; e < E; e += stride) {
        int r = eidx(ei, is64, e);
        int c = eidx(ei, is64, e + E);
        int pos = atomicAdd(&g_cur[r], 1);
        g_col[pos] = c;
    }
}

// ---------------------------------------------------------------------------
// agg1: t[r] = (sum_{c in adj(r)} x[c]) / max(deg,1) + x[r]
// Warp per row; half-warp per neighbor, float4 per lane (cols 4*(lane&15)..+3).
// ---------------------------------------------------------------------------
__global__ __launch_bounds__(512) void agg1_k(const float4* __restrict__ x4, int Nn) {
    int w = (blockIdx.x * blockDim.x + threadIdx.x) >> 5;
    if (w >= Nn) return;
    int lane = threadIdx.x & 31;
    int cl4 = lane & 15;
    int hi  = lane >> 4;
    int s = g_rowptr[w], e = g_rowptr[w + 1];
    float4 acc = make_float4(0.f, 0.f, 0.f, 0.f);
    int j = s;
    #pragma unroll 1
    for (; j + 8 <= e; j += 8) {
        int c0 = g_col[j +     hi];
        int c1 = g_col[j + 2 + hi];
        int c2 = g_col[j + 4 + hi];
        int c3 = g_col[j + 6 + hi];
        float4 v0 = __ldg(&x4[c0 * 16 + cl4]);
        float4 v1 = __ldg(&x4[c1 * 16 + cl4]);
        float4 v2 = __ldg(&x4[c2 * 16 + cl4]);
        float4 v3 = __ldg(&x4[c3 * 16 + cl4]);
        acc.x += (v0.x + v1.x) + (v2.x + v3.x);
        acc.y += (v0.y + v1.y) + (v2.y + v3.y);
        acc.z += (v0.z + v1.z) + (v2.z + v3.z);
        acc.w += (v0.w + v1.w) + (v2.w + v3.w);
    }
    #pragma unroll 1
    for (; j + 2 <= e; j += 2) {
        float4 v = __ldg(&x4[g_col[j + hi] * 16 + cl4]);
        acc.x += v.x; acc.y += v.y; acc.z += v.z; acc.w += v.w;
    }
    if (j < e && hi == 0) {
        float4 v = __ldg(&x4[g_col[j] * 16 + cl4]);
        acc.x += v.x; acc.y += v.y; acc.z += v.z; acc.w += v.w;
    }
    acc.x += __shfl_xor_sync(0xffffffffu, acc.x, 16);
    acc.y += __shfl_xor_sync(0xffffffffu, acc.y, 16);
    acc.z += __shfl_xor_sync(0xffffffffu, acc.z, 16);
    acc.w += __shfl_xor_sync(0xffffffffu, acc.w, 16);
    if (hi == 0) {
        float inv = 1.0f / fmaxf((float)(e - s), 1.0f);
        float4 xx = __ldg(&x4[w * 16 + cl4]);
        float4 o;
        o.x = acc.x * inv + xx.x;
        o.y = acc.y * inv + xx.y;
        o.z = acc.z * inv + xx.z;
        o.w = acc.w * inv + xx.w;
        ((float4*)g_t)[w * 16 + cl4] = o;
    }
}

// ---------------------------------------------------------------------------
// mm12: fused  h = relu(t @ W1 + b1);  p = h @ W2
// 128 threads, 4 warps, RPB rows/warp/iter; h lives only in smem.
// smem: sW1 32KB | sW2 32KB | sb1 512B | st 4*8*128*4B = 16KB  -> 82432 B
// ---------------------------------------------------------------------------
__global__ __launch_bounds__(128) void mm12_k(const float* __restrict__ W1,
                                              const float* __restrict__ b1,
                                              const float* __restrict__ W2,
                                              int Nn) {
    extern __shared__ char smem_[];
    float* sW1 = (float*)smem_;                 // [k][j] 64x128
    float* sW2 = (float*)(smem_ + 32768);       // [k][j] 128x64
    float* sb1 = (float*)(smem_ + 65536);
    float* st  = (float*)(smem_ + 66048);       // [warp][rr][128]

    int tid = threadIdx.x;
    for (int i = tid; i < D0 * D1; i += 128) sW1[i] = W1[i];
    for (int i = tid; i < D1 * D0; i += 128) sW2[i] = W2[i];
    if (tid < D1) sb1[tid] = b1[tid];
    __syncthreads();

    int warp = tid >> 5, lane = tid & 31;
    float* stw = st + warp * RPB * D1;
    float4 b4 = ((const float4*)sb1)[lane];
    int nwarps = gridDim.x * 4;
    int gw = blockIdx.x * 4 + warp;

    for (int base = gw * RPB; base < Nn; base += nwarps * RPB) {
        // stage t (conflict-free float2 per lane)
        #pragma unroll
        for (int rr = 0; rr < RPB; rr++) {
            int r = base + rr;
            if (r < Nn)
                ((float2*)(stw + rr * D1))[lane] = ((const float2*)g_t)[r * 32 + lane];
        }
        __syncwarp();

        // GEMM1: lane owns h cols 4lane..4lane+3
        uint64_t accA[RPB], accB[RPB];
        #pragma unroll
        for (int rr = 0; rr < RPB; rr++) { accA[rr] = 0ull; accB[rr] = 0ull; }

        #pragma unroll 2
        for (int k4 = 0; k4 < D0; k4 += 4) {
            float4 tv[RPB];
            #pragma unroll
            for (int rr = 0; rr < RPB; rr++)
                tv[rr] = *(const float4*)(stw + rr * D1 + k4);
            #pragma unroll
            for (int kk = 0; kk < 4; kk++) {
                ulonglong2 w2 = ((const ulonglong2*)(sW1 + (k4 + kk) * D1))[lane];
                #pragma unroll
                for (int rr = 0; rr < RPB; rr++) {
                    float tk = (kk == 0) ? tv[rr].x : (kk == 1) ? tv[rr].y
                             : (kk == 2) ? tv[rr].z : tv[rr].w;
                    uint64_t tt = pack2(tk);
                    fma2(accA[rr], tt, w2.x);
                    fma2(accB[rr], tt, w2.y);
                }
            }
        }
        __syncwarp();

        // h = relu(acc+b), restage into st (float4 per lane, conflict-free)
        #pragma unroll
        for (int rr = 0; rr < RPB; rr++) {
            float2 aa = *(float2*)&accA[rr];
            float2 bb = *(float2*)&accB[rr];
            float4 o;
            o.x = fmaxf(aa.x + b4.x, 0.f);
            o.y = fmaxf(aa.y + b4.y, 0.f);
            o.z = fmaxf(bb.x + b4.z, 0.f);
            o.w = fmaxf(bb.y + b4.w, 0.f);
            ((float4*)(stw + rr * D1))[lane] = o;
        }
        __syncwarp();

        // GEMM2: lane owns p cols 2lane..2lane+1
        uint64_t acc[RPB];
        #pragma unroll
        for (int rr = 0; rr < RPB; rr++) acc[rr] = 0ull;

        #pragma unroll 2
        for (int k4 = 0; k4 < D1; k4 += 4) {
            float4 hv[RPB];
            #pragma unroll
            for (int rr = 0; rr < RPB; rr++)
                hv[rr] = *(const float4*)(stw + rr * D1 + k4);
            #pragma unroll
            for (int kk = 0; kk < 4; kk++) {
                uint64_t w = ((const uint64_t*)(sW2 + (k4 + kk) * D0))[lane];
                #pragma unroll
                for (int rr = 0; rr < RPB; rr++) {
                    float hk = (kk == 0) ? hv[rr].x : (kk == 1) ? hv[rr].y
                             : (kk == 2) ? hv[rr].z : hv[rr].w;
                    fma2(acc[rr], pack2(hk), w);
                }
            }
        }

        #pragma unroll
        for (int rr = 0; rr < RPB; rr++) {
            int r = base + rr;
            if (r < Nn) ((float2*)g_p)[r * 32 + lane] = *(float2*)&acc[rr];
        }
        __syncwarp();
    }
}

// ---------------------------------------------------------------------------
// agg2: out[r] = (sum_{c in adj(r)} p[c]) / max(deg,1) + p[r] + b2
// Same half-warp float4 gather. Tail: re-zero g_cnt for next graph replay.
// ---------------------------------------------------------------------------
__global__ __launch_bounds__(512) void agg2_k(const float* __restrict__ b2,
                                              float* __restrict__ out, int Nn) {
    int w = (blockIdx.x * blockDim.x + threadIdx.x) >> 5;
    if (w >= Nn) return;
    int lane = threadIdx.x & 31;
    int cl4 = lane & 15;
    int hi  = lane >> 4;
    const float4* p4 = (const float4*)g_p;
    int s = g_rowptr[w], e = g_rowptr[w + 1];
    float4 acc = make_float4(0.f, 0.f, 0.f, 0.f);
    int j = s;
    #pragma unroll 1
    for (; j + 8 <= e; j += 8) {
        int c0 = g_col[j +     hi];
        int c1 = g_col[j + 2 + hi];
        int c2 = g_col[j + 4 + hi];
        int c3 = g_col[j + 6 + hi];
        float4 v0 = p4[c0 * 16 + cl4];
        float4 v1 = p4[c1 * 16 + cl4];
        float4 v2 = p4[c2 * 16 + cl4];
        float4 v3 = p4[c3 * 16 + cl4];
        acc.x += (v0.x + v1.x) + (v2.x + v3.x);
        acc.y += (v0.y + v1.y) + (v2.y + v3.y);
        acc.z += (v0.z + v1.z) + (v2.z + v3.z);
        acc.w += (v0.w + v1.w) + (v2.w + v3.w);
    }
    #pragma unroll 1
    for (; j + 2 <= e; j += 2) {
        float4 v = p4[g_col[j + hi] * 16 + cl4];
        acc.x += v.x; acc.y += v.y; acc.z += v.z; acc.w += v.w;
    }
    if (j < e && hi == 0) {
        float4 v = p4[g_col[j] * 16 + cl4];
        acc.x += v.x; acc.y += v.y; acc.z += v.z; acc.w += v.w;
    }
    acc.x += __shfl_xor_sync(0xffffffffu, acc.x, 16);
    acc.y += __shfl_xor_sync(0xffffffffu, acc.y, 16);
    acc.z += __shfl_xor_sync(0xffffffffu, acc.z, 16);
    acc.w += __shfl_xor_sync(0xffffffffu, acc.w, 16);
    if (hi == 0) {
        float inv = 1.0f / fmaxf((float)(e - s), 1.0f);
        float4 pp = p4[w * 16 + cl4];
        float4 bb = __ldg(&((const float4*)b2)[cl4]);
        float4 o;
        o.x = acc.x * inv + pp.x + bb.x;
        o.y = acc.y * inv + pp.y + bb.y;
        o.z = acc.z * inv + pp.z + bb.z;
        o.w = acc.w * inv + pp.w + bb.w;
        ((float4*)out)[w * 16 + cl4] = o;
    }
    if (lane == 0) g_cnt[w] = 0;
}

// ---------------------------------------------------------------------------
extern "C" void kernel_launch(void* const* d_in, const int* in_sizes, int n_in,
                              void* d_out, int out_size) {
    const float* x   = (const float*)d_in[0];
    const void*  ei  = d_in[1];
    const float* W1  = (const float*)d_in[2];
    const float* b1  = (const float*)d_in[3];
    const float* W2  = (const float*)d_in[4];
    const float* b2  = (const float*)d_in[5];
    float*       out = (float*)d_out;

    int Nn = in_sizes[0] / D0;       // 100000
    int E  = in_sizes[1] / 2;        // 1600000
    int nblk_scan = (Nn + 1023) / 1024;

    const int SM12 = 66048 + 4 * RPB * D1 * 4;   // 82432 B
    cudaFuncSetAttribute(mm12_k, cudaFuncAttributeMaxDynamicSharedMemorySize, SM12);

    hist_k<<<296, 1024>>>(ei, E);                        // 0
    scan_k<<<nblk_scan, 1024>>>(Nn, E);                  // 1
    fill_k<<<296, 1024>>>(ei, E);                        // 2
    agg1_k<<<(Nn * 32 + 511) / 512, 512>>>((const float4*)x, Nn);  // 3 <- profiled
    mm12_k<<<296, 128, SM12>>>(W1, b1, W2, Nn);          // 4
    agg2_k<<<(Nn * 32 + 511) / 512, 512>>>(b2, out, Nn); // 5
}